// round 6
// baseline (speedup 1.0000x reference)
#include <cuda_runtime.h>

// Problem constants (fixed shapes)
#define NB   64
#define NH   1024
#define NS   512
#define TPB  256
#define EPT  4                 // elements per thread (NH / TPB)
#define WST  16                // steps per smem window
#define NWIN (NS / WST)        // 32 windows
#define ROWLEN 1028            // padded smem row (floats), 16B-aligned rows, conflict-free LDS.128
#define NWARP (TPB / 32)

#define SBUF_HALF   (WST * ROWLEN)              // 16448 floats per buffer
#define SM_MASK_OFF (2 * SBUF_HALF)             // 32896
#define SM_WRED_OFF (SM_MASK_OFF + NS)          // 33408 (16B aligned: 133632 B)
#define SM_FLOATS   (SM_WRED_OFF + 2 * NWARP * 4)  // 33472
#define SMEM_BYTES  (SM_FLOATS * 4)             // 133888 B

__device__ __forceinline__ float clip1(float x) {
    return fminf(fmaxf(x, -1.0f), 1.0f);
}

// 3-value block reduction: warp butterfly + one smem stage (parity-selected buffer).
__device__ __forceinline__ void blk_reduce3(
    float pd, float ph, float ps,
    float* wred, int lane, int warp,
    float& dot, float& hh, float& ss)
{
    #pragma unroll
    for (int m = 16; m > 0; m >>= 1) {
        pd += __shfl_xor_sync(0xffffffffu, pd, m);
        ph += __shfl_xor_sync(0xffffffffu, ph, m);
        ps += __shfl_xor_sync(0xffffffffu, ps, m);
    }
    if (lane == 0)
        ((float4*)wred)[warp] = make_float4(pd, ph, ps, 0.0f);
    __syncthreads();
    float4 w0 = ((const float4*)wred)[0];
    float4 w1 = ((const float4*)wred)[1];
    float4 w2 = ((const float4*)wred)[2];
    float4 w3 = ((const float4*)wred)[3];
    float4 w4 = ((const float4*)wred)[4];
    float4 w5 = ((const float4*)wred)[5];
    float4 w6 = ((const float4*)wred)[6];
    float4 w7 = ((const float4*)wred)[7];
    dot = ((w0.x + w1.x) + (w2.x + w3.x)) + ((w4.x + w5.x) + (w6.x + w7.x));
    hh  = ((w0.y + w1.y) + (w2.y + w3.y)) + ((w4.y + w5.y) + (w6.y + w7.y));
    ss  = ((w0.z + w1.z) + (w2.z + w3.z)) + ((w4.z + w5.z) + (w6.z + w7.z));
}

extern "C" __global__ void __launch_bounds__(TPB, 1)
orth_scan_kernel(const float* __restrict__ tree,
                 const float* __restrict__ seq,
                 const float* __restrict__ mask,
                 float* __restrict__ out)
{
    extern __shared__ float sm[];
    float* sbuf = sm;                       // [2][WST][ROWLEN]  transposed windows
    float* msm  = sm + SM_MASK_OFF;         // [NS]
    float* wred = sm + SM_WRED_OFF;         // [2][NWARP*4]

    const int tid  = threadIdx.x;
    const int b    = blockIdx.x;
    const int lane = tid & 31;
    const int warp = tid >> 5;

    const float* seqb = seq + (size_t)b * NH * NS;

    // ---- load carry h (thread owns elements 4*tid .. 4*tid+3) ----
    float4 h4 = *(const float4*)(tree + b * NH + tid * EPT);
    float hx = h4.x, hy = h4.y, hz = h4.z, hw = h4.w;

    // ---- mask row -> smem ----
    msm[tid]       = mask[b * NS + tid];
    msm[tid + 256] = mask[b * NS + 256 + tid];

    // Staging geometry: round q covers rows q*64 .. q*64+63, 4 lanes per row
    // (each lane loads 16B = 4 consecutive t values) -> 8 lines per warp-LDG.
    const int srow = tid >> 2;   // 0..63 row-within-round
    const int sc   = tid & 3;    // 0..3 t-chunk

    // ---- stage window 0 into buffer 0 (transposed: sbuf[t][h]) ----
    {
        float4 v[16];
        #pragma unroll
        for (int q = 0; q < 16; q++) {
            int r = q * 64 + srow;
            v[q] = *(const float4*)(seqb + (size_t)r * NS + 4 * sc);
        }
        #pragma unroll
        for (int q = 0; q < 16; q++) {
            int r = q * 64 + srow;
            float* d0 = sbuf + (4 * sc) * ROWLEN + r;
            d0[0 * ROWLEN] = v[q].x;
            d0[1 * ROWLEN] = v[q].y;
            d0[2 * ROWLEN] = v[q].z;
            d0[3 * ROWLEN] = v[q].w;
        }
    }
    __syncthreads();

    // ---- initial reduce for step 0: dot(h0,s0), |h0|^2, |s0|^2 ----
    float4 scur = *(const float4*)(sbuf + 0 * ROWLEN + 4 * tid);
    float dot, hh, ss;
    {
        float pd = fmaf(hx, scur.x, fmaf(hy, scur.y, fmaf(hz, scur.z, hw * scur.w)));
        float ph = fmaf(hx, hx, fmaf(hy, hy, fmaf(hz, hz, hw * hw)));
        float ps = fmaf(scur.x, scur.x, fmaf(scur.y, scur.y, fmaf(scur.z, scur.z, scur.w * scur.w)));
        // prologue uses parity-1 buffer (as if t = -1)
        blk_reduce3(pd, ph, ps, wred + NWARP * 4, lane, warp, dot, hh, ss);
    }

    // ---- main scan ----
    for (int win = 0; win < NWIN; ++win) {
        float* cb = sbuf + (win & 1) * SBUF_HALF;        // current window buffer
        float* nb = sbuf + ((win & 1) ^ 1) * SBUF_HALF;  // next window buffer
        const bool notlast = (win + 1 < NWIN);
        float4 stg[16];

        #pragma unroll
        for (int local = 0; local < WST; ++local) {
            const int t = win * WST + local;

            // prefetch s_{t+1} (latency hidden behind scalar + update)
            float4 snext = make_float4(0.f, 0.f, 0.f, 0.f);
            if (local < WST - 1) {
                snext = *(const float4*)(cb + (local + 1) * ROWLEN + 4 * tid);
            } else if (notlast) {
                snext = *(const float4*)(nb + 0 * ROWLEN + 4 * tid);
            }
            const float m = msm[t];

            // scalar (redundant per thread): cos = dot / max(sqrt(hh*ss), eps)
            const float denom = fmaxf(__fsqrt_rn(hh * ss), 1e-8f);
            const float cosv  = __fdiv_rn(dot, denom);

            // elementwise update: h = clip(h + (s - h*cos)*m)
            hx = clip1(fmaf(m, fmaf(-cosv, hx, scur.x), hx));
            hy = clip1(fmaf(m, fmaf(-cosv, hy, scur.y), hy));
            hz = clip1(fmaf(m, fmaf(-cosv, hz, scur.z), hz));
            hw = clip1(fmaf(m, fmaf(-cosv, hw, scur.w), hw));

            // stage next window: LDG rounds {2L,2L+1} at locals 0..7
            if (notlast && local < 8) {
                const int q0 = 2 * local;
                const size_t toff = (size_t)(win + 1) * WST + 4 * sc;
                int r0 = q0 * 64 + srow;
                stg[q0]     = *(const float4*)(seqb + (size_t)r0 * NS + toff);
                stg[q0 + 1] = *(const float4*)(seqb + (size_t)(r0 + 64) * NS + toff);
            }

            if (t < NS - 1) {
                // partials for step t+1 (uses updated h and s_{t+1})
                float pd = fmaf(hx, snext.x, fmaf(hy, snext.y, fmaf(hz, snext.z, hw * snext.w)));
                float ph = fmaf(hx, hx, fmaf(hy, hy, fmaf(hz, hz, hw * hw)));
                float ps = fmaf(snext.x, snext.x,
                          fmaf(snext.y, snext.y,
                          fmaf(snext.z, snext.z, snext.w * snext.w)));

                // stage next window: STS rounds {2(L-7),2(L-7)+1} at locals 7..14
                // (7-step gap after the matching LDG; last STS at local 14 is
                //  published by that step's __syncthreads before local 15's LDS of nb)
                if (notlast && local >= 7 && local <= 14) {
                    const int q0 = 2 * (local - 7);
                    #pragma unroll
                    for (int k = 0; k < 2; k++) {
                        const int q = q0 + k;
                        const int r = q * 64 + srow;
                        float* d0 = nb + (4 * sc) * ROWLEN + r;
                        d0[0 * ROWLEN] = stg[q].x;
                        d0[1 * ROWLEN] = stg[q].y;
                        d0[2 * ROWLEN] = stg[q].z;
                        d0[3 * ROWLEN] = stg[q].w;
                    }
                }

                // parity-double-buffered cross-warp reduce (kills WAR race)
                blk_reduce3(pd, ph, ps, wred + (t & 1) * (NWARP * 4),
                            lane, warp, dot, hh, ss);
                scur = snext;
            }
        }
    }

    // ---- write final h ----
    *(float4*)(out + b * NH + tid * EPT) = make_float4(hx, hy, hz, hw);
}

extern "C" void kernel_launch(void* const* d_in, const int* in_sizes, int n_in,
                              void* d_out, int out_size)
{
    const float* tree = nullptr;
    const float* seq  = nullptr;
    const float* mask = nullptr;
    for (int i = 0; i < n_in; i++) {
        if (in_sizes[i] == NB * NH)           tree = (const float*)d_in[i];
        else if (in_sizes[i] == NB * NH * NS) seq  = (const float*)d_in[i];
        else if (in_sizes[i] == NB * NS)      mask = (const float*)d_in[i];
    }
    float* out = (float*)d_out;

    cudaFuncSetAttribute(orth_scan_kernel,
                         cudaFuncAttributeMaxDynamicSharedMemorySize, SMEM_BYTES);
    orth_scan_kernel<<<NB, TPB, SMEM_BYTES>>>(tree, seq, mask, out);
}

// round 12
// speedup vs baseline: 1.0763x; 1.0763x over previous
#include <cuda_runtime.h>

// Problem constants (fixed shapes)
#define NB   64
#define NH   1024
#define NS   512
#define TPB  256
#define EPT  4                 // elements per thread (NH / TPB)
#define WST  16                // steps per smem window
#define NWIN (NS / WST)        // 32 windows
#define ROWLEN 1028            // padded smem row (floats), 16B-aligned rows, conflict-free LDS.128
#define NWARP (TPB / 32)

#define SBUF_HALF   (WST * ROWLEN)              // 16448 floats per buffer
#define SM_MASK_OFF (2 * SBUF_HALF)             // 32896
#define SM_WRED_OFF (SM_MASK_OFF + NS)          // 33408 (16B aligned: 133632 B)
#define SM_FLOATS   (SM_WRED_OFF + 2 * NWARP * 4)  // 33472
#define SMEM_BYTES  (SM_FLOATS * 4)             // 133888 B

__device__ __forceinline__ float clip1(float x) {
    return fminf(fmaxf(x, -1.0f), 1.0f);
}

// 3-value block reduction: warp butterfly + one smem stage (parity-selected buffer).
// (redux.sync.add.f32 is NOT available on sm_103 — float redux is sm_100a-only.)
__device__ __forceinline__ void blk_reduce3(
    float pd, float ph, float ps,
    float* wred, int lane, int warp,
    float& dot, float& hh, float& ss)
{
    // three independent 5-level chains; they interleave so total latency ~5*26
    #pragma unroll
    for (int m = 16; m > 0; m >>= 1) {
        pd += __shfl_xor_sync(0xffffffffu, pd, m);
        ph += __shfl_xor_sync(0xffffffffu, ph, m);
        ps += __shfl_xor_sync(0xffffffffu, ps, m);
    }
    if (lane == 0)
        ((float4*)wred)[warp] = make_float4(pd, ph, ps, 0.0f);
    __syncthreads();
    float4 w0 = ((const float4*)wred)[0];
    float4 w1 = ((const float4*)wred)[1];
    float4 w2 = ((const float4*)wred)[2];
    float4 w3 = ((const float4*)wred)[3];
    float4 w4 = ((const float4*)wred)[4];
    float4 w5 = ((const float4*)wred)[5];
    float4 w6 = ((const float4*)wred)[6];
    float4 w7 = ((const float4*)wred)[7];
    dot = ((w0.x + w1.x) + (w2.x + w3.x)) + ((w4.x + w5.x) + (w6.x + w7.x));
    hh  = ((w0.y + w1.y) + (w2.y + w3.y)) + ((w4.y + w5.y) + (w6.y + w7.y));
    ss  = ((w0.z + w1.z) + (w2.z + w3.z)) + ((w4.z + w5.z) + (w6.z + w7.z));
}

extern "C" __global__ void __launch_bounds__(TPB, 1)
orth_scan_kernel(const float* __restrict__ tree,
                 const float* __restrict__ seq,
                 const float* __restrict__ mask,
                 float* __restrict__ out)
{
    extern __shared__ float sm[];
    float* sbuf = sm;                       // [2][WST][ROWLEN]  transposed windows
    float* msm  = sm + SM_MASK_OFF;         // [NS]
    float* wred = sm + SM_WRED_OFF;         // [2][NWARP*4]

    const int tid  = threadIdx.x;
    const int b    = blockIdx.x;
    const int lane = tid & 31;
    const int warp = tid >> 5;

    const float* seqb = seq + (size_t)b * NH * NS;

    // ---- load carry h (thread owns elements 4*tid .. 4*tid+3) ----
    float4 h4 = *(const float4*)(tree + b * NH + tid * EPT);
    float hx = h4.x, hy = h4.y, hz = h4.z, hw = h4.w;

    // ---- mask row -> smem ----
    msm[tid]       = mask[b * NS + tid];
    msm[tid + 256] = mask[b * NS + 256 + tid];

    // Staging geometry: round q covers rows q*64 .. q*64+63, 4 lanes per row
    // (each lane loads 16B = 4 consecutive t values) -> 8 lines per warp-LDG.
    const int srow = tid >> 2;   // 0..63 row-within-round
    const int sc   = tid & 3;    // 0..3 t-chunk

    // ---- stage window 0 into buffer 0 (transposed: sbuf[t][h]) ----
    {
        float4 v[16];
        #pragma unroll
        for (int q = 0; q < 16; q++) {
            int r = q * 64 + srow;
            v[q] = *(const float4*)(seqb + (size_t)r * NS + 4 * sc);
        }
        #pragma unroll
        for (int q = 0; q < 16; q++) {
            int r = q * 64 + srow;
            float* d0 = sbuf + (4 * sc) * ROWLEN + r;
            d0[0 * ROWLEN] = v[q].x;
            d0[1 * ROWLEN] = v[q].y;
            d0[2 * ROWLEN] = v[q].z;
            d0[3 * ROWLEN] = v[q].w;
        }
    }
    __syncthreads();

    // ---- initial reduce for step 0: dot(h0,s0), |h0|^2, |s0|^2 ----
    float4 scur = *(const float4*)(sbuf + 0 * ROWLEN + 4 * tid);
    float dot, hh, ss;
    {
        float d01 = fmaf(hy, scur.y, hx * scur.x);
        float d23 = fmaf(hw, scur.w, hz * scur.z);
        float h01 = fmaf(hy, hy, hx * hx);
        float h23 = fmaf(hw, hw, hz * hz);
        float s01 = fmaf(scur.y, scur.y, scur.x * scur.x);
        float s23 = fmaf(scur.w, scur.w, scur.z * scur.z);
        // prologue uses parity-1 buffer (as if t = -1)
        blk_reduce3(d01 + d23, h01 + h23, s01 + s23,
                    wred + NWARP * 4, lane, warp, dot, hh, ss);
    }

    // ---- main scan ----
    for (int win = 0; win < NWIN; ++win) {
        float* cb = sbuf + (win & 1) * SBUF_HALF;        // current window buffer
        float* nb = sbuf + ((win & 1) ^ 1) * SBUF_HALF;  // next window buffer
        const bool notlast = (win + 1 < NWIN);
        float4 stg[16];

        #pragma unroll
        for (int local = 0; local < WST; ++local) {
            const int t = win * WST + local;

            // prefetch s_{t+1} (latency hidden behind scalar + update)
            float4 snext = make_float4(0.f, 0.f, 0.f, 0.f);
            if (local < WST - 1) {
                snext = *(const float4*)(cb + (local + 1) * ROWLEN + 4 * tid);
            } else if (notlast) {
                snext = *(const float4*)(nb + 0 * ROWLEN + 4 * tid);
            }
            const float m = msm[t];

            // scalar (redundant per thread):
            //   cos = dot / max(sqrt(hh*ss), 1e-8)  ==  dot * rsqrt(max(hh*ss, 1e-16))
            // MUFU.RSQ (lat 16) replaces IEEE sqrt+div (~90-100 cyc) on the chain.
            const float arg  = fmaxf(hh * ss, 1e-16f);
            const float cosv = dot * rsqrtf(arg);

            // elementwise update: h = clip(h + (s - h*cos)*m)
            hx = clip1(fmaf(m, fmaf(-cosv, hx, scur.x), hx));
            hy = clip1(fmaf(m, fmaf(-cosv, hy, scur.y), hy));
            hz = clip1(fmaf(m, fmaf(-cosv, hz, scur.z), hz));
            hw = clip1(fmaf(m, fmaf(-cosv, hw, scur.w), hw));

            // stage next window: LDG rounds {2L,2L+1} at locals 0..7
            if (notlast && local < 8) {
                const int q0 = 2 * local;
                const size_t toff = (size_t)(win + 1) * WST + 4 * sc;
                int r0 = q0 * 64 + srow;
                stg[q0]     = *(const float4*)(seqb + (size_t)r0 * NS + toff);
                stg[q0 + 1] = *(const float4*)(seqb + (size_t)(r0 + 64) * NS + toff);
            }

            if (t < NS - 1) {
                // partials for step t+1 (uses updated h and s_{t+1}); balanced trees
                float d01 = fmaf(hy, snext.y, hx * snext.x);
                float d23 = fmaf(hw, snext.w, hz * snext.z);
                float h01 = fmaf(hy, hy, hx * hx);
                float h23 = fmaf(hw, hw, hz * hz);
                float s01 = fmaf(snext.y, snext.y, snext.x * snext.x);
                float s23 = fmaf(snext.w, snext.w, snext.z * snext.z);

                // stage next window: STS rounds {2(L-7),2(L-7)+1} at locals 7..14
                // (7-step gap after the matching LDG; last STS at local 14 is
                //  published by that step's __syncthreads before local 15's LDS of nb)
                if (notlast && local >= 7 && local <= 14) {
                    const int q0 = 2 * (local - 7);
                    #pragma unroll
                    for (int k = 0; k < 2; k++) {
                        const int q = q0 + k;
                        const int r = q * 64 + srow;
                        float* d0 = nb + (4 * sc) * ROWLEN + r;
                        d0[0 * ROWLEN] = stg[q].x;
                        d0[1 * ROWLEN] = stg[q].y;
                        d0[2 * ROWLEN] = stg[q].z;
                        d0[3 * ROWLEN] = stg[q].w;
                    }
                }

                // parity-double-buffered cross-warp reduce (kills WAR race)
                blk_reduce3(d01 + d23, h01 + h23, s01 + s23,
                            wred + (t & 1) * (NWARP * 4),
                            lane, warp, dot, hh, ss);
                scur = snext;
            }
        }
    }

    // ---- write final h ----
    *(float4*)(out + b * NH + tid * EPT) = make_float4(hx, hy, hz, hw);
}

extern "C" void kernel_launch(void* const* d_in, const int* in_sizes, int n_in,
                              void* d_out, int out_size)
{
    const float* tree = nullptr;
    const float* seq  = nullptr;
    const float* mask = nullptr;
    for (int i = 0; i < n_in; i++) {
        if (in_sizes[i] == NB * NH)           tree = (const float*)d_in[i];
        else if (in_sizes[i] == NB * NH * NS) seq  = (const float*)d_in[i];
        else if (in_sizes[i] == NB * NS)      mask = (const float*)d_in[i];
    }
    float* out = (float*)d_out;

    cudaFuncSetAttribute(orth_scan_kernel,
                         cudaFuncAttributeMaxDynamicSharedMemorySize, SMEM_BYTES);
    orth_scan_kernel<<<NB, TPB, SMEM_BYTES>>>(tree, seq, mask, out);
}